// round 9
// baseline (speedup 1.0000x reference)
#include <cuda_runtime.h>
#include <cuda_bf16.h>
#include <math.h>

#define TT 4096          // tokens
#define HH 1024          // hidden
#define FF 3584          // ffn dim
#define EE 8             // experts
#define SLOT_CAP (TT*2 + EE*128)   // 9216, each expert segment padded to 128
#define NTILES (SLOT_CAP/128)      // 72

// ---------------- small routing scratch only (~140KB of statics) ------------
__device__ int   d_sel[TT * 2];
__device__ float d_rw [TT * 2];
__device__ int   d_tile_expert[NTILES];
__device__ int   d_slot_token[SLOT_CAP];
__device__ float d_slot_w[SLOT_CAP];

// dynamic smem layout for the megakernel
#define G_BYTES     (128 * 132 * 4)            // g tile, m-major [128][132]
#define STAGE_BYTES (16 * 132 * 4)             // one [16][132] staging buffer
#define SMEM_TOTAL  (G_BYTES + 3*STAGE_BYTES + 1024)   // ~94.5KB

// ---------------- zero the output (it is poisoned before timing) ------------
__global__ void zero_out_kernel(float4* __restrict__ out) {
    int i = blockIdx.x * blockDim.x + threadIdx.x;
    if (i < TT * (HH / 4)) out[i] = make_float4(0.f, 0.f, 0.f, 0.f);
}

// ---------------- router: one warp per token --------------------------------
__global__ void router_kernel(const float* __restrict__ x,
                              const float* __restrict__ gw) {
    int gtid = blockIdx.x * blockDim.x + threadIdx.x;
    int t    = gtid >> 5;
    int lane = gtid & 31;
    if (t >= TT) return;
    const float* xt = x + (size_t)t * HH;

    float l[EE];
#pragma unroll
    for (int e = 0; e < EE; e++) {
        float s = 0.f;
        for (int h = lane; h < HH; h += 32) s += xt[h] * gw[e * HH + h];
#pragma unroll
        for (int o = 16; o; o >>= 1) s += __shfl_xor_sync(0xffffffffu, s, o);
        l[e] = s;
    }
    if (lane == 0) {
        int e0 = 0;
#pragma unroll
        for (int e = 1; e < EE; e++) if (l[e] > l[e0]) e0 = e;   // tie -> lowest idx
        int e1 = -1;
#pragma unroll
        for (int e = 0; e < EE; e++)
            if (e != e0 && (e1 < 0 || l[e] > l[e1])) e1 = e;
        // normalized top-2 softmax weights: p0/(p0+p1) = 1/(1+exp(l1-l0))
        float w0 = 1.f / (1.f + expf(l[e1] - l[e0]));
        float w1 = 1.f - w0;
        d_sel[2*t] = e0; d_sel[2*t+1] = e1;
        d_rw [2*t] = w0; d_rw [2*t+1] = w1;
    }
}

// ---------------- build: counts + offsets + deterministic slot assignment ---
// ONE block, 256 threads (8 warps), shared-memory counters only.
__global__ void build_kernel() {
    __shared__ int s_counts[EE];
    __shared__ int s_off[EE + 1];
    int tid = threadIdx.x;

    for (int i = tid; i < SLOT_CAP; i += 256) {
        d_slot_token[i] = -1;
        d_slot_w[i] = 0.f;
    }
    if (tid < EE) s_counts[tid] = 0;
    __syncthreads();

    for (int i = tid; i < 2 * TT; i += 256)
        atomicAdd(&s_counts[d_sel[i]], 1);
    __syncthreads();

    if (tid == 0) {
        int off = 0;
        for (int e = 0; e < EE; e++) {
            s_off[e] = off;
            int padded = (s_counts[e] + 127) & ~127;
            int t0 = off >> 7, nt = padded >> 7;
            for (int i = 0; i < nt; i++) d_tile_expert[t0 + i] = e;
            off += padded;
        }
        s_off[EE] = off;
        for (int i = off >> 7; i < NTILES; i++) d_tile_expert[i] = -1;
    }
    __syncthreads();

    int wid = tid >> 5, lane = tid & 31;
    if (wid < EE) {
        int base_off = s_off[wid];
        int pos = 0;
        for (int base = 0; base < 2 * TT; base += 32) {   // 2*TT % 32 == 0
            int i = base + lane;
            bool mine = (d_sel[i] == wid);
            unsigned m = __ballot_sync(0xffffffffu, mine);
            if (mine) {
                int rank = __popc(m & ((1u << lane) - 1u));
                int slot = base_off + pos + rank;
                d_slot_token[slot] = i >> 1;
                d_slot_w[slot]     = d_rw[i];
            }
            pos += __popc(m);
        }
    }
}

// ---------------- megakernel: up-proj + SwiGLU + down-proj + combine --------
// Block = (f-block of 128, slot-tile of 128). 512 threads.
// Stage A: g[128m x 128f] = silu(X W1^T) * (X W3^T) * route_w  -> smem
// Stage B: for each of 8 h-tiles: P = g @ W2[e, htile, fblock]^T,
//          atomicAdd P into out[token, h]. Padding rows skipped.
__global__ __launch_bounds__(512, 1)
void moe_fused_kernel(const float* __restrict__ x,
                      const float* __restrict__ W1,
                      const float* __restrict__ W3,
                      const float* __restrict__ W2,
                      float* __restrict__ out) {
    int te = d_tile_expert[blockIdx.y];
    if (te < 0) return;
    int tileBase = blockIdx.y * 128;
    int fblock   = blockIdx.x;           // 0..27

    extern __shared__ char smem[];
    float (*gsm)[132] = (float (*)[132])smem;                      // [m][f] pad4
    float (*As)[132]  = (float (*)[132])(smem + G_BYTES);          // x / W2 stage
    float (*B1s)[132] = (float (*)[132])(smem + G_BYTES + STAGE_BYTES);
    float (*B3s)[132] = (float (*)[132])(smem + G_BYTES + 2*STAGE_BYTES);
    int*   rowtok = (int*)(smem + G_BYTES + 3*STAGE_BYTES);
    float* roww   = (float*)(rowtok + 128);

    int tid = threadIdx.x;
    if (tid < 128) {
        rowtok[tid] = d_slot_token[tileBase + tid];
        roww[tid]   = d_slot_w[tileBase + tid];
    }
    __syncthreads();

    const float4* X4 = (const float4*)x;
    const float4* P1 = (const float4*)(W1 + (size_t)te * FF * HH
                                          + (size_t)fblock * 128 * HH);
    const float4* P3 = (const float4*)(W3 + (size_t)te * FF * HH
                                          + (size_t)fblock * 128 * HH);
    const int K4 = HH / 4;        // 256

    int ty = tid >> 5;            // 0..15
    int tx = tid & 31;            // 0..31
    int m0 = ty << 3;             // 8 rows per thread
    int n0 = tx << 2;             // 4 cols per thread

    int lr = tid >> 2;            // load row 0..127
    int lc = tid & 3;             // load chunk 0..3
    int ltok = rowtok[lr];

    // ---------------- stage A: up-proj ----------------
    {
        float a1[8][4], a3[8][4];
#pragma unroll
        for (int i = 0; i < 8; i++)
#pragma unroll
            for (int j = 0; j < 4; j++) { a1[i][j] = 0.f; a3[i][j] = 0.f; }

        for (int k0 = 0; k0 < HH; k0 += 16) {
            int kb = k0 >> 2;
            float4 va = make_float4(0.f, 0.f, 0.f, 0.f);
            if (ltok >= 0) va = X4[(size_t)ltok * K4 + kb + lc];
            float4 v1 = P1[(size_t)lr * K4 + kb + lc];
            float4 v3 = P3[(size_t)lr * K4 + kb + lc];
            As [lc*4+0][lr] = va.x; As [lc*4+1][lr] = va.y;
            As [lc*4+2][lr] = va.z; As [lc*4+3][lr] = va.w;
            B1s[lc*4+0][lr] = v1.x; B1s[lc*4+1][lr] = v1.y;
            B1s[lc*4+2][lr] = v1.z; B1s[lc*4+3][lr] = v1.w;
            B3s[lc*4+0][lr] = v3.x; B3s[lc*4+1][lr] = v3.y;
            B3s[lc*4+2][lr] = v3.z; B3s[lc*4+3][lr] = v3.w;
            __syncthreads();
#pragma unroll
            for (int kk = 0; kk < 16; kk++) {
                float a[8];
#pragma unroll
                for (int i = 0; i < 8; i++) a[i] = As[kk][m0 + i];
                float4 b1 = *(const float4*)&B1s[kk][n0];
                float4 b3 = *(const float4*)&B3s[kk][n0];
#pragma unroll
                for (int i = 0; i < 8; i++) {
                    a1[i][0] += a[i] * b1.x; a1[i][1] += a[i] * b1.y;
                    a1[i][2] += a[i] * b1.z; a1[i][3] += a[i] * b1.w;
                    a3[i][0] += a[i] * b3.x; a3[i][1] += a[i] * b3.y;
                    a3[i][2] += a[i] * b3.z; a3[i][3] += a[i] * b3.w;
                }
            }
            __syncthreads();
        }

        // g = silu(h1) * h3 * route_w  -> gsm[m][f] (coalesced float4 rows)
#pragma unroll
        for (int i = 0; i < 8; i++) {
            int row = m0 + i;
            float w = roww[row];
            float4 v;
            float h1, h3;
            h1 = a1[i][0]; h3 = a3[i][0]; v.x = (h1 / (1.f + expf(-h1))) * h3 * w;
            h1 = a1[i][1]; h3 = a3[i][1]; v.y = (h1 / (1.f + expf(-h1))) * h3 * w;
            h1 = a1[i][2]; h3 = a3[i][2]; v.z = (h1 / (1.f + expf(-h1))) * h3 * w;
            h1 = a1[i][3]; h3 = a3[i][3]; v.w = (h1 / (1.f + expf(-h1))) * h3 * w;
            *(float4*)&gsm[row][n0] = v;
        }
    }
    __syncthreads();

    // ---------------- stage B: down-proj + atomic combine ----------------
    // out[token, h] += sum_f g[m, f] * W2[e, h, f],   f in this fblock's 128
    const float* W2e = W2 + (size_t)te * HH * FF + (size_t)fblock * 128;
    for (int ht = 0; ht < 8; ht++) {
        float acc[8][4];
#pragma unroll
        for (int i = 0; i < 8; i++)
#pragma unroll
            for (int j = 0; j < 4; j++) acc[i][j] = 0.f;

        for (int ks = 0; ks < 8; ks++) {
            // load W2 slice: rows h (128 of this h-tile), cols f (16 of k-step)
            const float4* v4 = (const float4*)(W2e + (size_t)(ht * 128 + lr) * FF
                                                   + ks * 16 + lc * 4);
            float4 vb = *v4;
            As[lc*4+0][lr] = vb.x; As[lc*4+1][lr] = vb.y;
            As[lc*4+2][lr] = vb.z; As[lc*4+3][lr] = vb.w;
            __syncthreads();
#pragma unroll
            for (int kk = 0; kk < 16; kk++) {
                int kf = ks * 16 + kk;
                float a[8];
#pragma unroll
                for (int i = 0; i < 8; i++) a[i] = gsm[m0 + i][kf];
                float4 b = *(const float4*)&As[kk][n0];
#pragma unroll
                for (int i = 0; i < 8; i++) {
                    acc[i][0] += a[i] * b.x; acc[i][1] += a[i] * b.y;
                    acc[i][2] += a[i] * b.z; acc[i][3] += a[i] * b.w;
                }
            }
            __syncthreads();
        }

#pragma unroll
        for (int i = 0; i < 8; i++) {
            int row = m0 + i;
            int tok = rowtok[row];
            if (tok >= 0) {
                float* dst = out + (size_t)tok * HH + ht * 128 + n0;
                atomicAdd(dst + 0, acc[i][0]);
                atomicAdd(dst + 1, acc[i][1]);
                atomicAdd(dst + 2, acc[i][2]);
                atomicAdd(dst + 3, acc[i][3]);
            }
        }
    }
}

extern "C" void kernel_launch(void* const* d_in, const int* in_sizes, int n_in,
                              void* d_out, int out_size) {
    // Identify inputs by size (element-count OR byte-count), positional fallback.
    const float* x  = nullptr;
    const float* gw = nullptr;
    const float* wbig[3] = {nullptr, nullptr, nullptr};
    int nb = 0;
    for (int i = 0; i < n_in; i++) {
        const float* p = (const float*)d_in[i];
        long long s = in_sizes[i];
        if (s == (long long)TT * HH || s == (long long)TT * HH * 4)      x = p;
        else if (s == (long long)EE * HH || s == (long long)EE * HH * 4) gw = p;
        else if (nb < 3) wbig[nb++] = p;
    }
    if (!x || !gw || nb < 3) {   // setup_inputs() dict order
        x  = (const float*)d_in[0];
        gw = (const float*)d_in[1];
        wbig[0] = (const float*)d_in[2];
        wbig[1] = (const float*)d_in[3];
        wbig[2] = (const float*)d_in[4];
    }
    const float* w1 = wbig[0];   // [8,3584,1024]
    const float* w2 = wbig[1];   // [8,1024,3584]
    const float* w3 = wbig[2];   // [8,3584,1024]
    float* out = (float*)d_out;

    static int smem_set = 0;
    if (!smem_set) {
        cudaFuncSetAttribute(moe_fused_kernel,
                             cudaFuncAttributeMaxDynamicSharedMemorySize,
                             SMEM_TOTAL);
        smem_set = 1;
    }

    zero_out_kernel<<<(TT * (HH/4) + 255) / 256, 256>>>((float4*)out);
    router_kernel<<<(TT * 32 + 255) / 256, 256>>>(x, gw);
    build_kernel<<<1, 256>>>();

    dim3 grid(FF / 128, NTILES);
    moe_fused_kernel<<<grid, 512, SMEM_TOTAL>>>(x, w1, w3, w2, out);
}

// round 13
// speedup vs baseline: 2.4183x; 2.4183x over previous
#include <cuda_runtime.h>
#include <cuda_bf16.h>
#include <cstdint>
#include <math.h>

#define TT 4096          // tokens
#define HH 1024          // hidden
#define FF 3584          // ffn dim
#define EE 8             // experts
#define SLOT_CAP (TT*2 + EE*128)   // 9216
#define NTILES (SLOT_CAP/128)      // 72

// ---------------- small routing scratch only (~140KB of statics) ------------
__device__ int   d_sel[TT * 2];
__device__ float d_rw [TT * 2];
__device__ int   d_tile_expert[NTILES];
__device__ int   d_slot_token[SLOT_CAP];
__device__ float d_slot_w[SLOT_CAP];

// ---------------- dynamic smem layout (uint32 words / bytes) -----------------
// SM_TOK:  int rowtok[128]            @ 0
// SM_RW:   float roww[128]            @ 512
// SM_G:    tf32 g[128][132]           @ 1024    (67584 B)
// SM_XS:   tf32 Xs[128][36]           @ 68608   (18432 B)  | aliased by W2s in stage B
// SM_W1S:  tf32 W1s[128][36]          @ 87040   (18432 B)
// SM_W3S:  tf32 W3s[128][36]          @ 105472  (18432 B)
#define SM_TOK   0
#define SM_RW    512
#define SM_G     1024
#define SM_XS    68608
#define SM_W1S   87040
#define SM_W3S   105472
#define SMEM_TOTAL 123904

// ---------------- helpers ----------------------------------------------------
__device__ __forceinline__ uint32_t f2tf32(float f) {
    uint32_t r;
    asm("cvt.rna.tf32.f32 %0, %1;" : "=r"(r) : "f"(f));
    return r;
}
__device__ __forceinline__ void mma_tf32_16n8k8(float c[4],
                                                const uint32_t a[4],
                                                const uint32_t b[2]) {
    asm volatile(
        "mma.sync.aligned.m16n8k8.row.col.f32.tf32.tf32.f32 "
        "{%0,%1,%2,%3}, {%4,%5,%6,%7}, {%8,%9}, {%0,%1,%2,%3};"
        : "+f"(c[0]), "+f"(c[1]), "+f"(c[2]), "+f"(c[3])
        : "r"(a[0]), "r"(a[1]), "r"(a[2]), "r"(a[3]), "r"(b[0]), "r"(b[1]));
}

// ---------------- zero the output (it is poisoned before timing) ------------
__global__ void zero_out_kernel(float4* __restrict__ out) {
    int i = blockIdx.x * blockDim.x + threadIdx.x;
    if (i < TT * (HH / 4)) out[i] = make_float4(0.f, 0.f, 0.f, 0.f);
}

// ---------------- router: one warp per token (fp32 exact) -------------------
__global__ void router_kernel(const float* __restrict__ x,
                              const float* __restrict__ gw) {
    int gtid = blockIdx.x * blockDim.x + threadIdx.x;
    int t    = gtid >> 5;
    int lane = gtid & 31;
    if (t >= TT) return;
    const float* xt = x + (size_t)t * HH;

    float l[EE];
#pragma unroll
    for (int e = 0; e < EE; e++) {
        float s = 0.f;
        for (int h = lane; h < HH; h += 32) s += xt[h] * gw[e * HH + h];
#pragma unroll
        for (int o = 16; o; o >>= 1) s += __shfl_xor_sync(0xffffffffu, s, o);
        l[e] = s;
    }
    if (lane == 0) {
        int e0 = 0;
#pragma unroll
        for (int e = 1; e < EE; e++) if (l[e] > l[e0]) e0 = e;
        int e1 = -1;
#pragma unroll
        for (int e = 0; e < EE; e++)
            if (e != e0 && (e1 < 0 || l[e] > l[e1])) e1 = e;
        float w0 = 1.f / (1.f + expf(l[e1] - l[e0]));
        float w1 = 1.f - w0;
        d_sel[2*t] = e0; d_sel[2*t+1] = e1;
        d_rw [2*t] = w0; d_rw [2*t+1] = w1;
    }
}

// ---------------- build: counts + offsets + deterministic slots -------------
__global__ void build_kernel() {
    __shared__ int s_counts[EE];
    __shared__ int s_off[EE + 1];
    int tid = threadIdx.x;

    for (int i = tid; i < SLOT_CAP; i += 256) {
        d_slot_token[i] = -1;
        d_slot_w[i] = 0.f;
    }
    if (tid < EE) s_counts[tid] = 0;
    __syncthreads();

    for (int i = tid; i < 2 * TT; i += 256)
        atomicAdd(&s_counts[d_sel[i]], 1);
    __syncthreads();

    if (tid == 0) {
        int off = 0;
        for (int e = 0; e < EE; e++) {
            s_off[e] = off;
            int padded = (s_counts[e] + 127) & ~127;
            int t0 = off >> 7, nt = padded >> 7;
            for (int i = 0; i < nt; i++) d_tile_expert[t0 + i] = e;
            off += padded;
        }
        s_off[EE] = off;
        for (int i = off >> 7; i < NTILES; i++) d_tile_expert[i] = -1;
    }
    __syncthreads();

    int wid = tid >> 5, lane = tid & 31;
    if (wid < EE) {
        int base_off = s_off[wid];
        int pos = 0;
        for (int base = 0; base < 2 * TT; base += 32) {
            int i = base + lane;
            bool mine = (d_sel[i] == wid);
            unsigned m = __ballot_sync(0xffffffffu, mine);
            if (mine) {
                int rank = __popc(m & ((1u << lane) - 1u));
                int slot = base_off + pos + rank;
                d_slot_token[slot] = i >> 1;
                d_slot_w[slot]     = d_rw[i];
            }
            pos += __popc(m);
        }
    }
}

// ---------------- tf32 mma.sync megakernel ----------------------------------
// Block = (fblock 0..27, slot-tile 0..71), 512 threads = 16 warps as 4x4.
// Warp tile 32m x 32n. Stage A: h1/h3 over K=1024 (32-wide chunks);
// SwiGLU in regs -> g (tf32) smem; Stage B: g @ W2^T per 128-h tile ->
// atomicAdd into out.
__global__ __launch_bounds__(512, 1)
void moe_mma_kernel(const float* __restrict__ x,
                    const float* __restrict__ W1,
                    const float* __restrict__ W3,
                    const float* __restrict__ W2,
                    float* __restrict__ out) {
    int te = d_tile_expert[blockIdx.y];
    if (te < 0) return;
    int tileBase = blockIdx.y * 128;
    int fblock   = blockIdx.x;

    extern __shared__ char smem[];
    int*      rowtok = (int*)(smem + SM_TOK);
    float*    roww   = (float*)(smem + SM_RW);
    uint32_t* gsm    = (uint32_t*)(smem + SM_G);     // [128][132]
    uint32_t* xs     = (uint32_t*)(smem + SM_XS);    // [128][36]
    uint32_t* w1s    = (uint32_t*)(smem + SM_W1S);   // [128][36]
    uint32_t* w3s    = (uint32_t*)(smem + SM_W3S);   // [128][36]
    uint32_t* w2s    = xs;                           // stage B alias

    int tid  = threadIdx.x;
    int w    = tid >> 5;
    int lane = tid & 31;
    int m0w  = (w >> 2) << 5;      // warp row origin (0,32,64,96)
    int n0w  = (w & 3) << 5;       // warp col origin
    int lr4  = lane >> 2;          // 0..7
    int lc4  = lane & 3;           // 0..3

    if (tid < 128) {
        rowtok[tid] = d_slot_token[tileBase + tid];
        roww[tid]   = d_slot_w[tileBase + tid];
    }
    __syncthreads();

    const float4* X4  = (const float4*)x;
    const float4* W14 = (const float4*)W1;
    const float4* W34 = (const float4*)W3;
    const float4* W24 = (const float4*)W2;
    size_t w1base = ((size_t)te * FF + (size_t)fblock * 128) * 256;  // float4 units

    // load indices for staging (per thread: 2 float4 per buffer per chunk)
    int sr  = tid >> 2;            // staging row 0..127
    int sc4 = tid & 3;             // float4 col 0..3 (of 8)
    int stok = rowtok[sr];

    // ---------------- stage A: h1/h3 accumulators ----------------
    float c1[2][4][4], c3[2][4][4];
#pragma unroll
    for (int mt = 0; mt < 2; mt++)
#pragma unroll
        for (int nt = 0; nt < 4; nt++)
#pragma unroll
            for (int q = 0; q < 4; q++) { c1[mt][nt][q] = 0.f; c3[mt][nt][q] = 0.f; }

    for (int kc = 0; kc < 32; kc++) {
        // stage 32-wide K chunk of X, W1, W3 (convert fp32 -> tf32 bits)
#pragma unroll
        for (int half = 0; half < 2; half++) {
            int c4 = sc4 + half * 4;       // 0..7
            float4 vx = make_float4(0.f, 0.f, 0.f, 0.f);
            if (stok >= 0) vx = X4[(size_t)stok * 256 + kc * 8 + c4];
            float4 v1 = W14[w1base + (size_t)sr * 256 + kc * 8 + c4];
            float4 v3 = W34[w1base + (size_t)sr * 256 + kc * 8 + c4];
            int o = sr * 36 + c4 * 4;
            xs [o+0] = f2tf32(vx.x); xs [o+1] = f2tf32(vx.y);
            xs [o+2] = f2tf32(vx.z); xs [o+3] = f2tf32(vx.w);
            w1s[o+0] = f2tf32(v1.x); w1s[o+1] = f2tf32(v1.y);
            w1s[o+2] = f2tf32(v1.z); w1s[o+3] = f2tf32(v1.w);
            w3s[o+0] = f2tf32(v3.x); w3s[o+1] = f2tf32(v3.y);
            w3s[o+2] = f2tf32(v3.z); w3s[o+3] = f2tf32(v3.w);
        }
        __syncthreads();

#pragma unroll
        for (int ks = 0; ks < 4; ks++) {
            int k0 = ks * 8;
            uint32_t a[2][4];
#pragma unroll
            for (int mt = 0; mt < 2; mt++) {
                int rb = m0w + mt * 16;
                a[mt][0] = xs[(rb + lr4)     * 36 + k0 + lc4];
                a[mt][1] = xs[(rb + lr4 + 8) * 36 + k0 + lc4];
                a[mt][2] = xs[(rb + lr4)     * 36 + k0 + lc4 + 4];
                a[mt][3] = xs[(rb + lr4 + 8) * 36 + k0 + lc4 + 4];
            }
            uint32_t b1[4][2], b3[4][2];
#pragma unroll
            for (int nt = 0; nt < 4; nt++) {
                int nb = n0w + nt * 8;
                b1[nt][0] = w1s[(nb + lr4) * 36 + k0 + lc4];
                b1[nt][1] = w1s[(nb + lr4) * 36 + k0 + lc4 + 4];
                b3[nt][0] = w3s[(nb + lr4) * 36 + k0 + lc4];
                b3[nt][1] = w3s[(nb + lr4) * 36 + k0 + lc4 + 4];
            }
#pragma unroll
            for (int mt = 0; mt < 2; mt++)
#pragma unroll
                for (int nt = 0; nt < 4; nt++) {
                    mma_tf32_16n8k8(c1[mt][nt], a[mt], b1[nt]);
                    mma_tf32_16n8k8(c3[mt][nt], a[mt], b3[nt]);
                }
        }
        __syncthreads();
    }

    // ---------------- SwiGLU: g = silu(h1)*h3*route_w -> gsm (tf32) ----------
#pragma unroll
    for (int mt = 0; mt < 2; mt++) {
        int r0 = m0w + mt * 16 + lr4;
        int r1 = r0 + 8;
        float w0 = roww[r0], w1r = roww[r1];
#pragma unroll
        for (int nt = 0; nt < 4; nt++) {
            int cA = n0w + nt * 8 + lc4 * 2;
            float h1, h3, g;
            h1 = c1[mt][nt][0]; h3 = c3[mt][nt][0];
            g = (h1 / (1.f + expf(-h1))) * h3 * w0;
            gsm[r0 * 132 + cA]     = f2tf32(g);
            h1 = c1[mt][nt][1]; h3 = c3[mt][nt][1];
            g = (h1 / (1.f + expf(-h1))) * h3 * w0;
            gsm[r0 * 132 + cA + 1] = f2tf32(g);
            h1 = c1[mt][nt][2]; h3 = c3[mt][nt][2];
            g = (h1 / (1.f + expf(-h1))) * h3 * w1r;
            gsm[r1 * 132 + cA]     = f2tf32(g);
            h1 = c1[mt][nt][3]; h3 = c3[mt][nt][3];
            g = (h1 / (1.f + expf(-h1))) * h3 * w1r;
            gsm[r1 * 132 + cA + 1] = f2tf32(g);
        }
    }
    __syncthreads();

    // ---------------- stage B: out += g @ W2tile^T ----------------
    int tok0[2], tok1[2];
#pragma unroll
    for (int mt = 0; mt < 2; mt++) {
        tok0[mt] = rowtok[m0w + mt * 16 + lr4];
        tok1[mt] = rowtok[m0w + mt * 16 + lr4 + 8];
    }

    for (int ht = 0; ht < 8; ht++) {
        float co[2][4][4];
#pragma unroll
        for (int mt = 0; mt < 2; mt++)
#pragma unroll
            for (int nt = 0; nt < 4; nt++)
#pragma unroll
                for (int q = 0; q < 4; q++) co[mt][nt][q] = 0.f;

        for (int kc = 0; kc < 4; kc++) {       // K=128 in chunks of 32
            // stage W2 chunk: rows h (128), cols f (32) of this fblock
#pragma unroll
            for (int half = 0; half < 2; half++) {
                int c4 = sc4 + half * 4;
                float4 v = W24[((size_t)te * HH + ht * 128 + sr) * 896
                               + (size_t)fblock * 32 + kc * 8 + c4];
                int o = sr * 36 + c4 * 4;
                w2s[o+0] = f2tf32(v.x); w2s[o+1] = f2tf32(v.y);
                w2s[o+2] = f2tf32(v.z); w2s[o+3] = f2tf32(v.w);
            }
            __syncthreads();

#pragma unroll
            for (int ks = 0; ks < 4; ks++) {
                int kg = kc * 32 + ks * 8;     // k index into g
                int k0 = ks * 8;               // k index into w2s
                uint32_t a[2][4];
#pragma unroll
                for (int mt = 0; mt < 2; mt++) {
                    int rb = m0w + mt * 16;
                    a[mt][0] = gsm[(rb + lr4)     * 132 + kg + lc4];
                    a[mt][1] = gsm[(rb + lr4 + 8) * 132 + kg + lc4];
                    a[mt][2] = gsm[(rb + lr4)     * 132 + kg + lc4 + 4];
                    a[mt][3] = gsm[(rb + lr4 + 8) * 132 + kg + lc4 + 4];
                }
#pragma unroll
                for (int nt = 0; nt < 4; nt++) {
                    int nb = n0w + nt * 8;
                    uint32_t b[2];
                    b[0] = w2s[(nb + lr4) * 36 + k0 + lc4];
                    b[1] = w2s[(nb + lr4) * 36 + k0 + lc4 + 4];
#pragma unroll
                    for (int mt = 0; mt < 2; mt++)
                        mma_tf32_16n8k8(co[mt][nt], a[mt], b);
                }
            }
            __syncthreads();
        }

        // atomic combine into out
#pragma unroll
        for (int mt = 0; mt < 2; mt++) {
#pragma unroll
            for (int nt = 0; nt < 4; nt++) {
                int hcol = ht * 128 + n0w + nt * 8 + lc4 * 2;
                if (tok0[mt] >= 0) {
                    float* dst = out + (size_t)tok0[mt] * HH + hcol;
                    atomicAdd(dst,     co[mt][nt][0]);
                    atomicAdd(dst + 1, co[mt][nt][1]);
                }
                if (tok1[mt] >= 0) {
                    float* dst = out + (size_t)tok1[mt] * HH + hcol;
                    atomicAdd(dst,     co[mt][nt][2]);
                    atomicAdd(dst + 1, co[mt][nt][3]);
                }
            }
        }
    }
}

extern "C" void kernel_launch(void* const* d_in, const int* in_sizes, int n_in,
                              void* d_out, int out_size) {
    const float* x  = nullptr;
    const float* gw = nullptr;
    const float* wbig[3] = {nullptr, nullptr, nullptr};
    int nb = 0;
    for (int i = 0; i < n_in; i++) {
        const float* p = (const float*)d_in[i];
        long long s = in_sizes[i];
        if (s == (long long)TT * HH || s == (long long)TT * HH * 4)      x = p;
        else if (s == (long long)EE * HH || s == (long long)EE * HH * 4) gw = p;
        else if (nb < 3) wbig[nb++] = p;
    }
    if (!x || !gw || nb < 3) {
        x  = (const float*)d_in[0];
        gw = (const float*)d_in[1];
        wbig[0] = (const float*)d_in[2];
        wbig[1] = (const float*)d_in[3];
        wbig[2] = (const float*)d_in[4];
    }
    const float* w1 = wbig[0];
    const float* w2 = wbig[1];
    const float* w3 = wbig[2];
    float* out = (float*)d_out;

    static int smem_set = 0;
    if (!smem_set) {
        cudaFuncSetAttribute(moe_mma_kernel,
                             cudaFuncAttributeMaxDynamicSharedMemorySize,
                             SMEM_TOTAL);
        smem_set = 1;
    }

    zero_out_kernel<<<(TT * (HH/4) + 255) / 256, 256>>>((float4*)out);
    router_kernel<<<(TT * 32 + 255) / 256, 256>>>(x, gw);
    build_kernel<<<1, 256>>>();

    dim3 grid(FF / 128, NTILES);
    moe_mma_kernel<<<grid, 512, SMEM_TOTAL>>>(x, w1, w3, w2, out);
}